// round 15
// baseline (speedup 1.0000x reference)
#include <cuda_runtime.h>
#include <math.h>

#define NB    8
#define NC    64
#define NPIX  1600
#define TOPK  10
#define TKPAD 12
#define NNZ   (NPIX * TOPK)
#define SORTN 2048
#define FULLW 0xFFFFFFFFu

// ---------------- static scratch (no runtime allocation) ----------------
__device__ float g_xx  [NB * NPIX];
__device__ unsigned long long g_skey[NB * NPIX];
__device__ unsigned short g_rs[NB * NPIX];
__device__ unsigned short g_re[NB * NPIX];
__device__ int   g_dvc [NB * NPIX];
__device__ int   g_topk[NB * NPIX * TKPAD];
__device__ float g_dv2 [NB * NPIX];
__device__ int   g_off [NB * (NPIX + 1)];
__device__ int   g_ecol[NB * NNZ];
__device__ float g_Z   [NB * NPIX * NC];           // RAW X@W + b (dv2 applied in k_edge)
__device__ float g_Y   [NB * NPIX * NC];
__device__ float g_Hf  [NB * NPIX * NC];
__device__ int   g_done [NB];                       // walk-slice completion counters
__device__ int   g_done2[NB];                       // vertex2 completion counters

__device__ __forceinline__ float4 f4add(float4 a, float4 b) {
    a.x += b.x; a.y += b.y; a.z += b.z; a.w += b.w; return a;
}
__device__ __forceinline__ float4 f4fma(float4 a, float4 z, float s) {
    a.x += z.x * s; a.y += z.y * s; a.z += z.z * s; a.w += z.w * s; return a;
}
__device__ __forceinline__ unsigned long long u64min_(unsigned long long a, unsigned long long b) { return a < b ? a : b; }
__device__ __forceinline__ unsigned long long u64max_(unsigned long long a, unsigned long long b) { return a > b ? a : b; }

// ---------------- K1: fused [layer-1 GEMM tiles | 1x1 conv + counter init]
__global__ void k_convgemm(const float* __restrict__ x,
                           const float* __restrict__ wc1,
                           const float* __restrict__ bc1,
                           const float* __restrict__ W,
                           const float* __restrict__ bias,
                           float* __restrict__ out)
{
    __shared__ float As[64 * 64];
    __shared__ float Ws[64 * 64];
    int t = threadIdx.x;

    if (blockIdx.x < 200) {
        int b  = blockIdx.x / 25;
        int r0 = (blockIdx.x - b * 25) * 64;
        const float* Xb = x + ((size_t)b * NPIX + r0) * NC;
        for (int i = t; i < 4096; i += 256) { As[i] = Xb[i]; Ws[i] = W[i]; }
        __syncthreads();
        int tx = t & 15, ty = t >> 4;
        int c4 = tx * 4, r4 = ty * 4;
        float acc[4][4];
        #pragma unroll
        for (int i = 0; i < 4; i++)
            #pragma unroll
            for (int j = 0; j < 4; j++) acc[i][j] = 0.f;
        for (int k = 0; k < 64; k += 4) {
            float4 w0 = *(const float4*)&Ws[(k+0)*64 + c4];
            float4 w1 = *(const float4*)&Ws[(k+1)*64 + c4];
            float4 w2 = *(const float4*)&Ws[(k+2)*64 + c4];
            float4 w3 = *(const float4*)&Ws[(k+3)*64 + c4];
            #pragma unroll
            for (int i = 0; i < 4; i++) {
                float4 a = *(const float4*)&As[(r4+i)*64 + k];
                acc[i][0] += a.x*w0.x + a.y*w1.x + a.z*w2.x + a.w*w3.x;
                acc[i][1] += a.x*w0.y + a.y*w1.y + a.z*w2.y + a.w*w3.y;
                acc[i][2] += a.x*w0.z + a.y*w1.z + a.z*w2.z + a.w*w3.z;
                acc[i][3] += a.x*w0.w + a.y*w1.w + a.z*w2.w + a.w*w3.w;
            }
        }
        float4 bv = *(const float4*)&bias[c4];
        #pragma unroll
        for (int i = 0; i < 4; i++) {
            int r = r0 + r4 + i;
            float4 o;
            o.x = acc[i][0] + bv.x;
            o.y = acc[i][1] + bv.y;
            o.z = acc[i][2] + bv.z;
            o.w = acc[i][3] + bv.w;
            *(float4*)&g_Z[((size_t)b*NPIX + r) * NC + c4] = o;   // raw
        }
    } else {
        int idx = blockIdx.x - 200;                 // 0..55
        int b = idx / 7;
        float* ws = As;
        if (t < NC) ws[t] = wc1[t];
        __syncthreads();
        int gid = idx * 256 + t;
        if (gid < NB * NPIX) g_dvc[gid] = 0;
        if (gid < NB) { out[gid] = 0.f; g_done[gid] = 0; g_done2[gid] = 0; }
        int p = (idx - b * 7) * 256 + t;
        if (p >= NPIX) return;
        const float* xb = x + (size_t)b * NC * NPIX;
        float acc = bc1[0];
        #pragma unroll
        for (int c = 0; c < NC; c++) acc += xb[c*NPIX + p] * ws[c];
        g_xx[b*NPIX + p] = fmaxf(acc, 0.f);
    }
}

// ---------------- K2: softmax + sort + run bounds (8 blocks)
__global__ __launch_bounds__(1024) void k_sortA()
{
    int b = blockIdx.x, t = threadIdx.x;
    __shared__ unsigned long long skey[SORTN];
    __shared__ float rf[1024];

    float v0 = g_xx[b*NPIX + t];
    float v1 = (t + 1024 < NPIX) ? g_xx[b*NPIX + t + 1024] : -3.4e38f;
    rf[t] = fmaxf(v0, v1); __syncthreads();
    for (int s = 512; s > 0; s >>= 1) { if (t < s) rf[t] = fmaxf(rf[t], rf[t+s]); __syncthreads(); }
    float mx = rf[0]; __syncthreads();
    float e0 = expf(v0 - mx);
    float e1 = (t + 1024 < NPIX) ? expf(v1 - mx) : 0.f;
    rf[t] = e0 + e1; __syncthreads();
    for (int s = 512; s > 0; s >>= 1) { if (t < s) rf[t] += rf[t+s]; __syncthreads(); }
    float inv = 1.f / rf[0]; __syncthreads();

    unsigned long long a0 = ((unsigned long long)__float_as_uint(e0 * inv) << 32) | (unsigned)t;
    unsigned long long a1 = (t + 1024 < NPIX)
        ? (((unsigned long long)__float_as_uint(e1 * inv) << 32) | (unsigned)(t + 1024))
        : 0xFFFFFFFFFFFFFFFFull;

    #define REGPHASE(KSZ, J) { \
        unsigned long long p0 = __shfl_xor_sync(FULLW, a0, (J)); \
        unsigned long long p1 = __shfl_xor_sync(FULLW, a1, (J)); \
        int i0 = t, i1 = t + 1024; \
        bool m0 = (((i0 & (J)) == 0) == ((i0 & (KSZ)) == 0)); \
        bool m1 = (((i1 & (J)) == 0) == ((i1 & (KSZ)) == 0)); \
        a0 = m0 ? u64min_(a0, p0) : u64max_(a0, p0); \
        a1 = m1 ? u64min_(a1, p1) : u64max_(a1, p1); }

    for (int ksz = 2; ksz <= 32; ksz <<= 1)
        for (int j = ksz >> 1; j >= 1; j >>= 1)
            REGPHASE(ksz, j);
    skey[t] = a0; skey[t + 1024] = a1; __syncthreads();

    for (int ksz = 64; ksz <= SORTN; ksz <<= 1) {
        int jstart = ksz >> 1;
        if (ksz == SORTN) {
            unsigned long long lo = u64min_(a0, a1), hi = u64max_(a0, a1);
            a0 = lo; a1 = hi;
            skey[t] = a0; skey[t + 1024] = a1; __syncthreads();
            jstart = 512;
        }
        for (int j = jstart; j >= 32; j >>= 1) {
            #pragma unroll
            for (int r = 0; r < 2; r++) {
                int i = t + r * 1024;
                int ixj = i ^ j;
                if (ixj > i) {
                    unsigned long long a = skey[i], c = skey[ixj];
                    bool up = ((i & ksz) == 0);
                    if ((a > c) == up) { skey[i] = c; skey[ixj] = a; }
                }
            }
            __syncthreads();
        }
        a0 = skey[t]; a1 = skey[t + 1024];
        for (int j = 16; j >= 1; j >>= 1)
            REGPHASE(ksz, j);
        skey[t] = a0; skey[t + 1024] = a1; __syncthreads();
    }

    for (int p = t; p < NPIX; p += 1024) {
        unsigned v = (unsigned)(skey[p] >> 32);
        int lo = 0, hi = p;
        while (lo < hi) { int m = (lo + hi) >> 1;
            if ((unsigned)(skey[m] >> 32) < v) lo = m + 1; else hi = m; }
        int lo2 = p + 1, hi2 = NPIX;
        while (lo2 < hi2) { int m = (lo2 + hi2) >> 1;
            if ((unsigned)(skey[m] >> 32) <= v) lo2 = m + 1; else hi2 = m; }
        g_skey[b*NPIX + p] = skey[p];
        g_rs[b*NPIX + p] = (unsigned short)lo;
        g_re[b*NPIX + p] = (unsigned short)(lo2 - 1);
    }
}

// ---------------- K3: top-k walk (8 slices/batch) + last-block scan & CSR fill
__global__ __launch_bounds__(256) void k_walk()
{
    int b = blockIdx.y, slice = blockIdx.x, t = threadIdx.x;
    __shared__ unsigned long long sk[NPIX];         // 12.8 KB
    __shared__ unsigned short rs[NPIX], re[NPIX];   // 6.4 KB
    __shared__ int off_s[NPIX + 1];                 // 6.4 KB
    __shared__ int cur_s[NPIX];                     // 6.4 KB
    __shared__ int wsum[8];
    __shared__ int isLast;

    for (int p = t; p < NPIX; p += 256) {
        sk[p] = g_skey[b*NPIX + p];
        rs[p] = g_rs[b*NPIX + p];
        re[p] = g_re[b*NPIX + p];
    }
    __syncthreads();

    if (t < 200) {
        int p = slice * 200 + t;
        int i = (int)(sk[p] & 0xFFFFFFFFu);
        float vi = __uint_as_float((unsigned)(sk[p] >> 32));

        int out[TOPK]; int cnt = 0;
        int a = rs[p], bnd = re[p];
        for (int q = a; q <= bnd && cnt < TOPK; q++)
            out[cnt++] = (int)(sk[q] & 0xFFFFFFFFu);
        int L = a - 1, R = bnd + 1;
        while (cnt < TOPK) {
            float dL = (L >= 0)   ? vi - __uint_as_float((unsigned)(sk[L] >> 32)) : 3.4e38f;
            float dR = (R < NPIX) ? __uint_as_float((unsigned)(sk[R] >> 32)) - vi : 3.4e38f;
            if (dL < dR) {
                int s2 = rs[L];
                for (int q = s2; q <= L && cnt < TOPK; q++)
                    out[cnt++] = (int)(sk[q] & 0xFFFFFFFFu);
                L = s2 - 1;
            } else if (dR < dL) {
                int e2 = re[R];
                for (int q = R; q <= e2 && cnt < TOPK; q++)
                    out[cnt++] = (int)(sk[q] & 0xFFFFFFFFu);
                R = e2 + 1;
            } else {                                  // exact distance tie: merge by idx
                int sL = rs[L], eR = re[R];
                int qa = sL, qb = R;
                while (cnt < TOPK && (qa <= L || qb <= eR)) {
                    int ia = (qa <= L)  ? (int)(sk[qa] & 0xFFFFFFFFu) : 0x7FFFFFFF;
                    int ib = (qb <= eR) ? (int)(sk[qb] & 0xFFFFFFFFu) : 0x7FFFFFFF;
                    if (ia < ib) { out[cnt++] = ia; qa++; }
                    else         { out[cnt++] = ib; qb++; }
                }
                L = sL - 1; R = eR + 1;
            }
        }
        bool has = false;
        #pragma unroll
        for (int j2 = 0; j2 < TOPK; j2++) has |= (out[j2] == i);
        if (!has) out[TOPK-1] = i;                    // reference self rule

        int base = (b*NPIX + i) * TKPAD;
        #pragma unroll
        for (int j2 = 0; j2 < TOPK; j2++) {
            g_topk[base + j2] = out[j2];
            atomicAdd(&g_dvc[b*NPIX + out[j2]], 1);
        }
    }

    // -------- release: this slice's writes, then bump counter
    __threadfence();
    __syncthreads();
    if (t == 0) isLast = (atomicAdd(&g_done[b], 1) == 7) ? 1 : 0;
    __syncthreads();
    if (!isLast) return;
    if (t == 0) __threadfence();                      // acquire
    __syncthreads();

    // -------- scan phase (256 threads, chunk of 7)
    int lane = t & 31, w = t >> 5;
    int c0 = t * 7, c1 = min(c0 + 7, NPIX);
    int dloc[7]; int csum = 0;
    for (int i = c0, k = 0; i < c1; i++, k++) { dloc[k] = g_dvc[b*NPIX + i]; csum += dloc[k]; }
    int incl = csum;
    #pragma unroll
    for (int d2 = 1; d2 < 32; d2 <<= 1) {
        int vv = __shfl_up_sync(FULLW, incl, d2);
        if (lane >= d2) incl += vv;
    }
    if (lane == 31) wsum[w] = incl;
    __syncthreads();
    if (t == 0) {
        int run = 0;
        #pragma unroll
        for (int i = 0; i < 8; i++) { int tmp = wsum[i]; wsum[i] = run; run += tmp; }
    }
    __syncthreads();
    int run = incl - csum + wsum[w];
    for (int i = c0, k = 0; i < c1; i++, k++) {
        off_s[i] = run;
        g_off[b*(NPIX+1) + i] = run;
        g_dv2[b*NPIX + i] = rsqrtf((float)dloc[k]);
        cur_s[i] = 0;
        run += dloc[k];
    }
    if (t == 0) { off_s[NPIX] = NNZ; g_off[b*(NPIX+1) + NPIX] = NNZ; }
    __syncthreads();

    // -------- CSR fill phase (smem cursors)
    for (int s2 = t; s2 < NNZ; s2 += 256) {
        int e = s2 / TOPK, j2 = s2 - e * TOPK;
        int v = g_topk[(b*NPIX + e) * TKPAD + j2];
        int ppos = atomicAdd(&cur_s[v], 1);
        g_ecol[b*NNZ + off_s[v] + ppos] = e;
    }
}

// ---------------- hyperedge gather with fused 0.1*dv2 scaling per vertex term
__global__ void k_edge()
{
    int b = blockIdx.y, t = threadIdx.x;
    int e  = blockIdx.x * 16 + (t >> 4);
    int c4 = (t & 15) * 4;
    const int* __restrict__ tk = &g_topk[(b*NPIX + e) * TKPAD];
    int4 i0 = *(const int4*)tk;
    int4 i1 = *(const int4*)(tk + 4);
    int2 i2 = *(const int2*)(tk + 8);
    const float* __restrict__ dvb = &g_dv2[b*NPIX];
    float4 acc = make_float4(0.f, 0.f, 0.f, 0.f);
    #define EDGET(V) { int v_ = (V); float s_ = 0.1f * dvb[v_]; \
        acc = f4fma(acc, *(const float4*)&g_Z[((b*NPIX + v_) << 6) + c4], s_); }
    EDGET(i0.x); EDGET(i0.y); EDGET(i0.z); EDGET(i0.w);
    EDGET(i1.x); EDGET(i1.y); EDGET(i1.z); EDGET(i1.w);
    EDGET(i2.x); EDGET(i2.y);
    #undef EDGET
    *(float4*)&g_Y[((b*NPIX + e) << 6) + c4] = acc;
}

// ---------------- layer-2 GEMM: Z = Hf@W + b (raw; dv2 applied in k_edge)
__global__ void k_gemm2(const float* __restrict__ W,
                        const float* __restrict__ bias)
{
    int b  = blockIdx.y;
    int r0 = blockIdx.x * 64;
    __shared__ float As[64 * 64];
    __shared__ float Ws[64 * 64];
    int t = threadIdx.x;
    const float* Xb = g_Hf + ((size_t)b * NPIX + r0) * NC;
    for (int i = t; i < 4096; i += 256) { As[i] = Xb[i]; Ws[i] = W[i]; }
    __syncthreads();

    int tx = t & 15, ty = t >> 4;
    int c4 = tx * 4, r4 = ty * 4;
    float acc[4][4];
    #pragma unroll
    for (int i = 0; i < 4; i++)
        #pragma unroll
        for (int j = 0; j < 4; j++) acc[i][j] = 0.f;

    for (int k = 0; k < 64; k += 4) {
        float4 w0 = *(const float4*)&Ws[(k+0)*64 + c4];
        float4 w1 = *(const float4*)&Ws[(k+1)*64 + c4];
        float4 w2 = *(const float4*)&Ws[(k+2)*64 + c4];
        float4 w3 = *(const float4*)&Ws[(k+3)*64 + c4];
        #pragma unroll
        for (int i = 0; i < 4; i++) {
            float4 a = *(const float4*)&As[(r4+i)*64 + k];
            acc[i][0] += a.x*w0.x + a.y*w1.x + a.z*w2.x + a.w*w3.x;
            acc[i][1] += a.x*w0.y + a.y*w1.y + a.z*w2.y + a.w*w3.y;
            acc[i][2] += a.x*w0.z + a.y*w1.z + a.z*w2.z + a.w*w3.z;
            acc[i][3] += a.x*w0.w + a.y*w1.w + a.z*w2.w + a.w*w3.w;
        }
    }
    float4 bv = *(const float4*)&bias[c4];
    #pragma unroll
    for (int i = 0; i < 4; i++) {
        int r = r0 + r4 + i;
        float4 o;
        o.x = acc[i][0] + bv.x;
        o.y = acc[i][1] + bv.y;
        o.z = acc[i][2] + bv.z;
        o.w = acc[i][3] + bv.w;
        *(float4*)&g_Z[((size_t)b*NPIX + r) * NC + c4] = o;
    }
}

// ---------------- layer-1 vertex gather: block per vertex, 16 slices float4
__global__ void k_vertex()
{
    int b = blockIdx.y, u = blockIdx.x, t = threadIdx.x;
    int c4 = (t & 15) * 4, s = t >> 4;
    __shared__ float4 red[256];
    int o0 = g_off[b*(NPIX+1) + u];
    int o1 = g_off[b*(NPIX+1) + u + 1];
    float4 acc = make_float4(0.f, 0.f, 0.f, 0.f);
    for (int p = o0 + s; p < o1; p += 16) {
        int e = g_ecol[b*NNZ + p];
        acc = f4add(acc, *(const float4*)&g_Y[((b*NPIX + e) << 6) + c4]);
    }
    red[t] = acc; __syncthreads();
    if (t < 128) red[t] = f4add(red[t], red[t+128]); __syncthreads();
    if (t < 64)  red[t] = f4add(red[t], red[t+64]);  __syncthreads();
    if (t < 32)  red[t] = f4add(red[t], red[t+32]);  __syncthreads();
    if (t < 16) {
        float4 tot = f4add(red[t], red[t+16]);
        float sc = g_dv2[b*NPIX + u];
        float4 o;
        o.x = fmaxf(tot.x * sc, 0.f);
        o.y = fmaxf(tot.y * sc, 0.f);
        o.z = fmaxf(tot.z * sc, 0.f);
        o.w = fmaxf(tot.w * sc, 0.f);
        *(float4*)&g_Hf[((b*NPIX + u) << 6) + t*4] = o;
    }
}

// ---------------- layer-2 vertex gather + last-block final conv/sum
__global__ void k_vertex2(const float* __restrict__ wc,
                          const float* __restrict__ bc,
                          float* __restrict__ out)
{
    int b = blockIdx.y, u = blockIdx.x, t = threadIdx.x;
    int c4 = (t & 15) * 4, s = t >> 4;
    __shared__ float4 red[256];
    __shared__ int isLast;
    int o0 = g_off[b*(NPIX+1) + u];
    int o1 = g_off[b*(NPIX+1) + u + 1];
    float4 acc = make_float4(0.f, 0.f, 0.f, 0.f);
    for (int p = o0 + s; p < o1; p += 16) {
        int e = g_ecol[b*NNZ + p];
        acc = f4add(acc, *(const float4*)&g_Y[((b*NPIX + e) << 6) + c4]);
    }
    red[t] = acc; __syncthreads();
    if (t < 128) red[t] = f4add(red[t], red[t+128]); __syncthreads();
    if (t < 64)  red[t] = f4add(red[t], red[t+64]);  __syncthreads();
    if (t < 32)  red[t] = f4add(red[t], red[t+32]);  __syncthreads();
    if (t < 16) {
        float4 tot = f4add(red[t], red[t+16]);
        float sc = g_dv2[b*NPIX + u];
        float4 o;
        o.x = fmaxf(tot.x * sc, 0.f);
        o.y = fmaxf(tot.y * sc, 0.f);
        o.z = fmaxf(tot.z * sc, 0.f);
        o.w = fmaxf(tot.w * sc, 0.f);
        *(float4*)&g_Hf[((b*NPIX + u) << 6) + t*4] = o;
    }

    // release + last-block detection
    __threadfence();
    __syncthreads();
    if (t == 0) isLast = (atomicAdd(&g_done2[b], 1) == NPIX - 1) ? 1 : 0;
    __syncthreads();
    if (!isLast) return;
    if (t == 0) __threadfence();                      // acquire
    __syncthreads();

    // final 1x1 conv + relu + sum for batch b
    float* ws = (float*)red;                          // reuse smem
    float* rsum = ((float*)red) + 64;
    if (t < NC) ws[t] = wc[t];
    __syncthreads();
    const float* hb = g_Hf + (size_t)b * NPIX * NC;   // raw reshape: (C, NPIX)
    float bb = bc[0];
    float lsum = 0.f;
    for (int p = t; p < NPIX; p += 256) {
        float a2 = bb;
        #pragma unroll
        for (int c = 0; c < NC; c++) a2 += hb[c*NPIX + p] * ws[c];
        lsum += fmaxf(a2, 0.f);
    }
    rsum[t] = lsum; __syncthreads();
    for (int s2 = 128; s2 > 0; s2 >>= 1) { if (t < s2) rsum[t] += rsum[t+s2]; __syncthreads(); }
    if (t == 0) out[b] = rsum[0];
}

// ---------------- launch ----------------
extern "C" void kernel_launch(void* const* d_in, const int* in_sizes, int n_in,
                              void* d_out, int out_size)
{
    const float* x      = (const float*)d_in[0];
    const float* w_con1 = (const float*)d_in[1];
    const float* b_con1 = (const float*)d_in[2];
    const float* W1     = (const float*)d_in[3];
    const float* b1     = (const float*)d_in[4];
    const float* W2     = (const float*)d_in[5];
    const float* b2     = (const float*)d_in[6];
    const float* w_con2 = (const float*)d_in[7];
    const float* b_con2 = (const float*)d_in[8];
    float* out = (float*)d_out;

    k_convgemm<<<256, 256>>>(x, w_con1, b_con1, W1, b1, out);
    k_sortA<<<NB, 1024>>>();
    k_walk<<<dim3(8, NB), 256>>>();                   // + scan + fill in last block

    // layer 1
    k_edge<<<dim3(NPIX / 16, NB), 256>>>();
    k_vertex<<<dim3(NPIX, NB), 256>>>();

    // layer 2
    k_gemm2<<<dim3(NPIX / 64, NB), 256>>>(W2, b2);
    k_edge<<<dim3(NPIX / 16, NB), 256>>>();
    k_vertex2<<<dim3(NPIX, NB), 256>>>(w_con2, b_con2, out);   // + final in last block
}

// round 16
// speedup vs baseline: 1.9531x; 1.9531x over previous
#include <cuda_runtime.h>
#include <math.h>

#define NB    8
#define NC    64
#define NPIX  1600
#define TOPK  10
#define TKPAD 12
#define NNZ   (NPIX * TOPK)
#define SORTN 2048
#define FULLW 0xFFFFFFFFu

// ---------------- static scratch (no runtime allocation) ----------------
__device__ float g_xx  [NB * NPIX];
__device__ unsigned long long g_skey[NB * NPIX];
__device__ unsigned short g_rs[NB * NPIX];
__device__ unsigned short g_re[NB * NPIX];
__device__ int   g_cur [NB * NPIX];                // slot cursor == DV after k_walk
__device__ int   g_topk[NB * NPIX * TKPAD];
__device__ int   g_ecol2[NB * NPIX * NPIX];        // fixed-stride vertex->edge lists (82 MB)
__device__ float g_Z   [NB * NPIX * NC];           // RAW X@W + b (dv2 applied in k_edge)
__device__ float g_Y   [NB * NPIX * NC];
__device__ float g_Hf  [NB * NPIX * NC];

__device__ __forceinline__ float4 f4add(float4 a, float4 b) {
    a.x += b.x; a.y += b.y; a.z += b.z; a.w += b.w; return a;
}
__device__ __forceinline__ float4 f4fma(float4 a, float4 z, float s) {
    a.x += z.x * s; a.y += z.y * s; a.z += z.z * s; a.w += z.w * s; return a;
}
__device__ __forceinline__ unsigned long long u64min_(unsigned long long a, unsigned long long b) { return a < b ? a : b; }
__device__ __forceinline__ unsigned long long u64max_(unsigned long long a, unsigned long long b) { return a > b ? a : b; }

// ---------------- K1: fused [layer-1 GEMM tiles | 1x1 conv + counter init]
__global__ void k_convgemm(const float* __restrict__ x,
                           const float* __restrict__ wc1,
                           const float* __restrict__ bc1,
                           const float* __restrict__ W,
                           const float* __restrict__ bias,
                           float* __restrict__ out)
{
    __shared__ float As[64 * 64];
    __shared__ float Ws[64 * 64];
    int t = threadIdx.x;

    if (blockIdx.x < 200) {
        int b  = blockIdx.x / 25;
        int r0 = (blockIdx.x - b * 25) * 64;
        const float* Xb = x + ((size_t)b * NPIX + r0) * NC;
        for (int i = t; i < 4096; i += 256) { As[i] = Xb[i]; Ws[i] = W[i]; }
        __syncthreads();
        int tx = t & 15, ty = t >> 4;
        int c4 = tx * 4, r4 = ty * 4;
        float acc[4][4];
        #pragma unroll
        for (int i = 0; i < 4; i++)
            #pragma unroll
            for (int j = 0; j < 4; j++) acc[i][j] = 0.f;
        for (int k = 0; k < 64; k += 4) {
            float4 w0 = *(const float4*)&Ws[(k+0)*64 + c4];
            float4 w1 = *(const float4*)&Ws[(k+1)*64 + c4];
            float4 w2 = *(const float4*)&Ws[(k+2)*64 + c4];
            float4 w3 = *(const float4*)&Ws[(k+3)*64 + c4];
            #pragma unroll
            for (int i = 0; i < 4; i++) {
                float4 a = *(const float4*)&As[(r4+i)*64 + k];
                acc[i][0] += a.x*w0.x + a.y*w1.x + a.z*w2.x + a.w*w3.x;
                acc[i][1] += a.x*w0.y + a.y*w1.y + a.z*w2.y + a.w*w3.y;
                acc[i][2] += a.x*w0.z + a.y*w1.z + a.z*w2.z + a.w*w3.z;
                acc[i][3] += a.x*w0.w + a.y*w1.w + a.z*w2.w + a.w*w3.w;
            }
        }
        float4 bv = *(const float4*)&bias[c4];
        #pragma unroll
        for (int i = 0; i < 4; i++) {
            int r = r0 + r4 + i;
            float4 o;
            o.x = acc[i][0] + bv.x;
            o.y = acc[i][1] + bv.y;
            o.z = acc[i][2] + bv.z;
            o.w = acc[i][3] + bv.w;
            *(float4*)&g_Z[((size_t)b*NPIX + r) * NC + c4] = o;   // raw
        }
    } else {
        int idx = blockIdx.x - 200;                 // 0..55
        int b = idx / 7;
        float* ws = As;
        if (t < NC) ws[t] = wc1[t];
        __syncthreads();
        int gid = idx * 256 + t;
        if (gid < NB * NPIX) g_cur[gid] = 0;
        if (gid < NB) out[gid] = 0.f;
        int p = (idx - b * 7) * 256 + t;
        if (p >= NPIX) return;
        const float* xb = x + (size_t)b * NC * NPIX;
        float acc = bc1[0];
        #pragma unroll
        for (int c = 0; c < NC; c++) acc += xb[c*NPIX + p] * ws[c];
        g_xx[b*NPIX + p] = fmaxf(acc, 0.f);
    }
}

// ---------------- K2: softmax + sort + run bounds (8 blocks)
__global__ __launch_bounds__(1024) void k_sortA()
{
    int b = blockIdx.x, t = threadIdx.x;
    __shared__ unsigned long long skey[SORTN];
    __shared__ float rf[1024];

    float v0 = g_xx[b*NPIX + t];
    float v1 = (t + 1024 < NPIX) ? g_xx[b*NPIX + t + 1024] : -3.4e38f;
    rf[t] = fmaxf(v0, v1); __syncthreads();
    for (int s = 512; s > 0; s >>= 1) { if (t < s) rf[t] = fmaxf(rf[t], rf[t+s]); __syncthreads(); }
    float mx = rf[0]; __syncthreads();
    float e0 = expf(v0 - mx);
    float e1 = (t + 1024 < NPIX) ? expf(v1 - mx) : 0.f;
    rf[t] = e0 + e1; __syncthreads();
    for (int s = 512; s > 0; s >>= 1) { if (t < s) rf[t] += rf[t+s]; __syncthreads(); }
    float inv = 1.f / rf[0]; __syncthreads();

    unsigned long long a0 = ((unsigned long long)__float_as_uint(e0 * inv) << 32) | (unsigned)t;
    unsigned long long a1 = (t + 1024 < NPIX)
        ? (((unsigned long long)__float_as_uint(e1 * inv) << 32) | (unsigned)(t + 1024))
        : 0xFFFFFFFFFFFFFFFFull;

    #define REGPHASE(KSZ, J) { \
        unsigned long long p0 = __shfl_xor_sync(FULLW, a0, (J)); \
        unsigned long long p1 = __shfl_xor_sync(FULLW, a1, (J)); \
        int i0 = t, i1 = t + 1024; \
        bool m0 = (((i0 & (J)) == 0) == ((i0 & (KSZ)) == 0)); \
        bool m1 = (((i1 & (J)) == 0) == ((i1 & (KSZ)) == 0)); \
        a0 = m0 ? u64min_(a0, p0) : u64max_(a0, p0); \
        a1 = m1 ? u64min_(a1, p1) : u64max_(a1, p1); }

    for (int ksz = 2; ksz <= 32; ksz <<= 1)
        for (int j = ksz >> 1; j >= 1; j >>= 1)
            REGPHASE(ksz, j);
    skey[t] = a0; skey[t + 1024] = a1; __syncthreads();

    for (int ksz = 64; ksz <= SORTN; ksz <<= 1) {
        int jstart = ksz >> 1;
        if (ksz == SORTN) {
            unsigned long long lo = u64min_(a0, a1), hi = u64max_(a0, a1);
            a0 = lo; a1 = hi;
            skey[t] = a0; skey[t + 1024] = a1; __syncthreads();
            jstart = 512;
        }
        for (int j = jstart; j >= 32; j >>= 1) {
            #pragma unroll
            for (int r = 0; r < 2; r++) {
                int i = t + r * 1024;
                int ixj = i ^ j;
                if (ixj > i) {
                    unsigned long long a = skey[i], c = skey[ixj];
                    bool up = ((i & ksz) == 0);
                    if ((a > c) == up) { skey[i] = c; skey[ixj] = a; }
                }
            }
            __syncthreads();
        }
        a0 = skey[t]; a1 = skey[t + 1024];
        for (int j = 16; j >= 1; j >>= 1)
            REGPHASE(ksz, j);
        skey[t] = a0; skey[t + 1024] = a1; __syncthreads();
    }

    for (int p = t; p < NPIX; p += 1024) {
        unsigned v = (unsigned)(skey[p] >> 32);
        int lo = 0, hi = p;
        while (lo < hi) { int m = (lo + hi) >> 1;
            if ((unsigned)(skey[m] >> 32) < v) lo = m + 1; else hi = m; }
        int lo2 = p + 1, hi2 = NPIX;
        while (lo2 < hi2) { int m = (lo2 + hi2) >> 1;
            if ((unsigned)(skey[m] >> 32) <= v) lo2 = m + 1; else hi2 = m; }
        g_skey[b*NPIX + p] = skey[p];
        g_rs[b*NPIX + p] = (unsigned short)lo;
        g_re[b*NPIX + p] = (unsigned short)(lo2 - 1);
    }
}

// ---------------- K3: top-k walk + direct fixed-stride edge-list scatter
__global__ __launch_bounds__(256) void k_walk()
{
    int b = blockIdx.y, slice = blockIdx.x, t = threadIdx.x;
    __shared__ unsigned long long sk[NPIX];
    __shared__ unsigned short rs[NPIX], re[NPIX];
    for (int p = t; p < NPIX; p += 256) {
        sk[p] = g_skey[b*NPIX + p];
        rs[p] = g_rs[b*NPIX + p];
        re[p] = g_re[b*NPIX + p];
    }
    __syncthreads();
    if (t >= 200) return;
    int p = slice * 200 + t;
    int i = (int)(sk[p] & 0xFFFFFFFFu);
    float vi = __uint_as_float((unsigned)(sk[p] >> 32));

    int out[TOPK]; int cnt = 0;
    int a = rs[p], bnd = re[p];
    for (int q = a; q <= bnd && cnt < TOPK; q++)
        out[cnt++] = (int)(sk[q] & 0xFFFFFFFFu);
    int L = a - 1, R = bnd + 1;
    while (cnt < TOPK) {
        float dL = (L >= 0)   ? vi - __uint_as_float((unsigned)(sk[L] >> 32)) : 3.4e38f;
        float dR = (R < NPIX) ? __uint_as_float((unsigned)(sk[R] >> 32)) - vi : 3.4e38f;
        if (dL < dR) {
            int s2 = rs[L];
            for (int q = s2; q <= L && cnt < TOPK; q++)
                out[cnt++] = (int)(sk[q] & 0xFFFFFFFFu);
            L = s2 - 1;
        } else if (dR < dL) {
            int e2 = re[R];
            for (int q = R; q <= e2 && cnt < TOPK; q++)
                out[cnt++] = (int)(sk[q] & 0xFFFFFFFFu);
            R = e2 + 1;
        } else {                                      // exact distance tie: merge by idx
            int sL = rs[L], eR = re[R];
            int qa = sL, qb = R;
            while (cnt < TOPK && (qa <= L || qb <= eR)) {
                int ia = (qa <= L)  ? (int)(sk[qa] & 0xFFFFFFFFu) : 0x7FFFFFFF;
                int ib = (qb <= eR) ? (int)(sk[qb] & 0xFFFFFFFFu) : 0x7FFFFFFF;
                if (ia < ib) { out[cnt++] = ia; qa++; }
                else         { out[cnt++] = ib; qb++; }
            }
            L = sL - 1; R = eR + 1;
        }
    }
    bool has = false;
    #pragma unroll
    for (int j2 = 0; j2 < TOPK; j2++) has |= (out[j2] == i);
    if (!has) out[TOPK-1] = i;                        // reference self rule

    int base = (b*NPIX + i) * TKPAD;
    #pragma unroll
    for (int j2 = 0; j2 < TOPK; j2++) {
        int v = out[j2];
        g_topk[base + j2] = v;
        int pos = atomicAdd(&g_cur[b*NPIX + v], 1);   // cursor doubles as DV count
        g_ecol2[(size_t)(b*NPIX + v) * NPIX + pos] = i;
    }
}

// ---------------- hyperedge gather with fused 0.1*rsqrt(DV) scaling
__global__ void k_edge()
{
    int b = blockIdx.y, t = threadIdx.x;
    int e  = blockIdx.x * 16 + (t >> 4);
    int c4 = (t & 15) * 4;
    const int* __restrict__ tk = &g_topk[(b*NPIX + e) * TKPAD];
    int4 i0 = *(const int4*)tk;
    int4 i1 = *(const int4*)(tk + 4);
    int2 i2 = *(const int2*)(tk + 8);
    const int* __restrict__ dvb = &g_cur[b*NPIX];
    float4 acc = make_float4(0.f, 0.f, 0.f, 0.f);
    #define EDGET(V) { int v_ = (V); float s_ = 0.1f * rsqrtf((float)dvb[v_]); \
        acc = f4fma(acc, *(const float4*)&g_Z[((b*NPIX + v_) << 6) + c4], s_); }
    EDGET(i0.x); EDGET(i0.y); EDGET(i0.z); EDGET(i0.w);
    EDGET(i1.x); EDGET(i1.y); EDGET(i1.z); EDGET(i1.w);
    EDGET(i2.x); EDGET(i2.y);
    #undef EDGET
    *(float4*)&g_Y[((b*NPIX + e) << 6) + c4] = acc;
}

// ---------------- layer-2 GEMM: Z = Hf@W + b (raw; dv2 applied in k_edge)
__global__ void k_gemm2(const float* __restrict__ W,
                        const float* __restrict__ bias)
{
    int b  = blockIdx.y;
    int r0 = blockIdx.x * 64;
    __shared__ float As[64 * 64];
    __shared__ float Ws[64 * 64];
    int t = threadIdx.x;
    const float* Xb = g_Hf + ((size_t)b * NPIX + r0) * NC;
    for (int i = t; i < 4096; i += 256) { As[i] = Xb[i]; Ws[i] = W[i]; }
    __syncthreads();

    int tx = t & 15, ty = t >> 4;
    int c4 = tx * 4, r4 = ty * 4;
    float acc[4][4];
    #pragma unroll
    for (int i = 0; i < 4; i++)
        #pragma unroll
        for (int j = 0; j < 4; j++) acc[i][j] = 0.f;

    for (int k = 0; k < 64; k += 4) {
        float4 w0 = *(const float4*)&Ws[(k+0)*64 + c4];
        float4 w1 = *(const float4*)&Ws[(k+1)*64 + c4];
        float4 w2 = *(const float4*)&Ws[(k+2)*64 + c4];
        float4 w3 = *(const float4*)&Ws[(k+3)*64 + c4];
        #pragma unroll
        for (int i = 0; i < 4; i++) {
            float4 a = *(const float4*)&As[(r4+i)*64 + k];
            acc[i][0] += a.x*w0.x + a.y*w1.x + a.z*w2.x + a.w*w3.x;
            acc[i][1] += a.x*w0.y + a.y*w1.y + a.z*w2.y + a.w*w3.y;
            acc[i][2] += a.x*w0.z + a.y*w1.z + a.z*w2.z + a.w*w3.z;
            acc[i][3] += a.x*w0.w + a.y*w1.w + a.z*w2.w + a.w*w3.w;
        }
    }
    float4 bv = *(const float4*)&bias[c4];
    #pragma unroll
    for (int i = 0; i < 4; i++) {
        int r = r0 + r4 + i;
        float4 o;
        o.x = acc[i][0] + bv.x;
        o.y = acc[i][1] + bv.y;
        o.z = acc[i][2] + bv.z;
        o.w = acc[i][3] + bv.w;
        *(float4*)&g_Z[((size_t)b*NPIX + r) * NC + c4] = o;
    }
}

// ---------------- vertex gather: block per vertex, 16 slices float4
__global__ void k_vertex()
{
    int b = blockIdx.y, u = blockIdx.x, t = threadIdx.x;
    int c4 = (t & 15) * 4, s = t >> 4;
    __shared__ float4 red[256];
    int dv = g_cur[b*NPIX + u];
    const int* __restrict__ row = &g_ecol2[(size_t)(b*NPIX + u) * NPIX];
    float4 acc = make_float4(0.f, 0.f, 0.f, 0.f);
    for (int p = s; p < dv; p += 16) {
        int e = row[p];
        acc = f4add(acc, *(const float4*)&g_Y[((b*NPIX + e) << 6) + c4]);
    }
    red[t] = acc; __syncthreads();
    if (t < 128) red[t] = f4add(red[t], red[t+128]); __syncthreads();
    if (t < 64)  red[t] = f4add(red[t], red[t+64]);  __syncthreads();
    if (t < 32)  red[t] = f4add(red[t], red[t+32]);  __syncthreads();
    if (t < 16) {
        float4 tot = f4add(red[t], red[t+16]);
        float sc = rsqrtf((float)dv);
        float4 o;
        o.x = fmaxf(tot.x * sc, 0.f);
        o.y = fmaxf(tot.y * sc, 0.f);
        o.z = fmaxf(tot.z * sc, 0.f);
        o.w = fmaxf(tot.w * sc, 0.f);
        *(float4*)&g_Hf[((b*NPIX + u) << 6) + t*4] = o;
    }
}

// ---------------- final 1x1 conv + relu + per-batch sum
__global__ void k_final(const float* __restrict__ wc,
                        const float* __restrict__ bc,
                        float* __restrict__ out)
{
    int b = blockIdx.y, t = threadIdx.x;
    __shared__ float ws[NC];
    __shared__ float red[256];
    if (t < NC) ws[t] = wc[t];
    __syncthreads();
    const float* hb = g_Hf + (size_t)b * NPIX * NC;   // raw reshape: (C, NPIX)
    int p = blockIdx.x * 256 + t;
    float lsum = 0.f;
    if (p < NPIX) {
        float acc = bc[0];
        #pragma unroll
        for (int c = 0; c < NC; c++) acc += hb[c*NPIX + p] * ws[c];
        lsum = fmaxf(acc, 0.f);
    }
    red[t] = lsum; __syncthreads();
    for (int s = 128; s > 0; s >>= 1) { if (t < s) red[t] += red[t+s]; __syncthreads(); }
    if (t == 0) atomicAdd(&out[b], red[0]);
}

// ---------------- launch ----------------
extern "C" void kernel_launch(void* const* d_in, const int* in_sizes, int n_in,
                              void* d_out, int out_size)
{
    const float* x      = (const float*)d_in[0];
    const float* w_con1 = (const float*)d_in[1];
    const float* b_con1 = (const float*)d_in[2];
    const float* W1     = (const float*)d_in[3];
    const float* b1     = (const float*)d_in[4];
    const float* W2     = (const float*)d_in[5];
    const float* b2     = (const float*)d_in[6];
    const float* w_con2 = (const float*)d_in[7];
    const float* b_con2 = (const float*)d_in[8];
    float* out = (float*)d_out;

    k_convgemm<<<256, 256>>>(x, w_con1, b_con1, W1, b1, out);
    k_sortA<<<NB, 1024>>>();
    k_walk<<<dim3(8, NB), 256>>>();                   // builds topk + edge lists + DV

    // layer 1
    k_edge<<<dim3(NPIX / 16, NB), 256>>>();
    k_vertex<<<dim3(NPIX, NB), 256>>>();

    // layer 2
    k_gemm2<<<dim3(NPIX / 64, NB), 256>>>(W2, b2);
    k_edge<<<dim3(NPIX / 16, NB), 256>>>();
    k_vertex<<<dim3(NPIX, NB), 256>>>();

    k_final<<<dim3(7, NB), 256>>>(w_con2, b_con2, out);
}